// round 1
// baseline (speedup 1.0000x reference)
#include <cuda_runtime.h>
#include <cstdint>

// Problem constants
#define B_   8
#define L_   2048
#define D_   64
#define TOPK_ 32

// Score kernel tiling
#define TQ 64          // query rows per block
#define CK 64          // keys per chunk
#define KSPLIT 2       // key-range splits per row-tile
#define KEYS_PER_BLK (L_ / KSPLIT)

// Selection
#define MARGIN 40      // candidate rank margin (>= TOPK_)
#define CAP    256     // candidate buffer capacity

// 134 MB global scratch for scores [B][Lq][Lk]
__device__ float g_scores[(size_t)B_ * L_ * L_];

// ---------------------------------------------------------------------------
// Kernel A: S[b][q][k] = dot(Q[b][q], K[b][k]) * 0.125 (fp32)
// grid (KSPLIT, L/TQ, B), block 256
// ---------------------------------------------------------------------------
__global__ __launch_bounds__(256) void score_kernel(
    const float* __restrict__ q, const float* __restrict__ k)
{
    __shared__ __align__(16) float Qs[TQ][68];   // pad 68: conflict-free strided f4 reads
    __shared__ __align__(16) float Ks[CK][68];

    const int b  = blockIdx.z;
    const int qt = blockIdx.y;
    const int ks = blockIdx.x;
    const int rowBase = qt * TQ;

    const float* qb = q + ((size_t)b * L_ + rowBase) * D_;
    const float* kb = k + (size_t)b * L_ * D_;
    float* sb = g_scores + ((size_t)b * L_ + rowBase) * L_;

    const int t  = threadIdx.x;
    const int tx = t & 15;   // key group
    const int ty = t >> 4;   // row group

    // Load Q tile (64x64 floats) as float4
    for (int i = t; i < TQ * 16; i += 256) {
        int row = i >> 4, dg = (i & 15) << 2;
        *(float4*)&Qs[row][dg] = *(const float4*)(qb + row * D_ + dg);
    }
    __syncthreads();

    for (int chunk = 0; chunk < KEYS_PER_BLK / CK; ++chunk) {
        const int keyBase = ks * KEYS_PER_BLK + chunk * CK;
        // Load K chunk
        for (int i = t; i < CK * 16; i += 256) {
            int row = i >> 4, dg = (i & 15) << 2;
            *(float4*)&Ks[row][dg] = *(const float4*)(kb + (size_t)(keyBase + row) * D_ + dg);
        }
        __syncthreads();

        float acc[4][4] = {};
        #pragma unroll
        for (int dg = 0; dg < D_; dg += 4) {
            float4 qv[4], kv[4];
            #pragma unroll
            for (int r = 0; r < 4; ++r) qv[r] = *(const float4*)&Qs[ty + 16 * r][dg];
            #pragma unroll
            for (int c = 0; c < 4; ++c) kv[c] = *(const float4*)&Ks[tx + 16 * c][dg];
            #pragma unroll
            for (int r = 0; r < 4; ++r)
                #pragma unroll
                for (int c = 0; c < 4; ++c) {
                    acc[r][c] = fmaf(qv[r].x, kv[c].x, acc[r][c]);
                    acc[r][c] = fmaf(qv[r].y, kv[c].y, acc[r][c]);
                    acc[r][c] = fmaf(qv[r].z, kv[c].z, acc[r][c]);
                    acc[r][c] = fmaf(qv[r].w, kv[c].w, acc[r][c]);
                }
        }

        #pragma unroll
        for (int r = 0; r < 4; ++r)
            #pragma unroll
            for (int c = 0; c < 4; ++c)
                sb[(size_t)(ty + 16 * r) * L_ + keyBase + tx + 16 * c] = acc[r][c] * 0.125f;
        __syncthreads();
    }
}

// ---------------------------------------------------------------------------
// Kernel B: per query row — threshold select candidates, refine with
// compensated float-float dot (~2^-48), exact top-32 (fp64 ordering),
// accumulate output.
// grid (B*L), block 256
// ---------------------------------------------------------------------------
__device__ __forceinline__ unsigned f2sortable(float f) {
    unsigned bb = __float_as_uint(f);
    return (bb & 0x80000000u) ? ~bb : (bb | 0x80000000u);
}

__device__ __forceinline__ void dot2_step(float a, float b, float& s, float& c) {
    float p  = __fmul_rn(a, b);
    float e  = __fmaf_rn(a, b, -p);          // exact product error
    float t1 = __fadd_rn(s, p);              // TwoSum(s, p)
    float bv = __fsub_rn(t1, s);
    float e2 = __fadd_rn(__fsub_rn(s, __fsub_rn(t1, bv)), __fsub_rn(p, bv));
    s = t1;
    c = __fadd_rn(c, __fadd_rn(e, e2));
}

__global__ __launch_bounds__(256) void select_kernel(
    const float* __restrict__ q, const float* __restrict__ k,
    const float* __restrict__ v, float* __restrict__ out)
{
    const int bid = blockIdx.x;
    const int b   = bid >> 11;       // / L_
    const int t   = threadIdx.x;
    const int lane = t & 31;
    const int wid  = t >> 5;

    __shared__ __align__(16) float qs[D_];
    __shared__ int     cand_idx[CAP];
    __shared__ double  cand_val[CAP];
    __shared__ int     sh_cnt;
    __shared__ int     warp_sums[8];
    __shared__ int     sh_total;
    __shared__ int     sel_idx[TOPK_];
    __shared__ float   sel_val[TOPK_];

    const float* srow = g_scores + (size_t)bid * L_;

    // Each thread owns 8 scores: indices 4t..4t+3 and 1024+4t..1024+4t+3
    const int i0 = 4 * t, i1 = (L_ / 2) + 4 * t;
    float4 s0 = *(const float4*)(srow + i0);
    float4 s1 = *(const float4*)(srow + i1);
    unsigned u[8];
    u[0] = f2sortable(s0.x); u[1] = f2sortable(s0.y);
    u[2] = f2sortable(s0.z); u[3] = f2sortable(s0.w);
    u[4] = f2sortable(s1.x); u[5] = f2sortable(s1.y);
    u[6] = f2sortable(s1.z); u[7] = f2sortable(s1.w);

    if (t < D_) qs[t] = q[((size_t)bid) * D_ + t];
    if (t == 0) sh_cnt = 0;

    // Binary search threshold tau (sortable space): MARGIN <= count(u>=tau) <= CAP
    unsigned lo = 0u, hi = 0xFFFFFFFFu, tau = 0u;
    for (int it = 0; it < 32; ++it) {
        unsigned mid = lo + ((hi - lo) >> 1);
        int c = 0;
        #pragma unroll
        for (int j = 0; j < 8; ++j) c += (u[j] >= mid);
        #pragma unroll
        for (int o = 16; o >= 1; o >>= 1) c += __shfl_xor_sync(0xffffffffu, c, o);
        if (lane == 0) warp_sums[wid] = c;
        __syncthreads();
        if (t == 0) {
            int tot = 0;
            #pragma unroll
            for (int w = 0; w < 8; ++w) tot += warp_sums[w];
            sh_total = tot;
        }
        __syncthreads();
        int total = sh_total;
        if (total >= MARGIN) {
            lo = mid; tau = mid;
            if (total <= CAP) break;
        } else {
            hi = mid;
        }
    }
    __syncthreads();

    // Collect candidates
    #pragma unroll
    for (int j = 0; j < 8; ++j) {
        if (u[j] >= tau) {
            int p = atomicAdd(&sh_cnt, 1);
            if (p < CAP) cand_idx[p] = (j < 4) ? (i0 + j) : (i1 + j - 4);
        }
    }
    __syncthreads();
    int n = sh_cnt; if (n > CAP) n = CAP;

    // Refine candidates with compensated float-float dot (matches fp64 ordering)
    const float* kb = k + (size_t)b * L_ * D_;
    for (int i = t; i < n; i += 256) {
        const float4* k4 = (const float4*)(kb + (size_t)cand_idx[i] * D_);
        const float4* q4 = (const float4*)qs;
        float s = 0.0f, c = 0.0f;
        #pragma unroll
        for (int dg = 0; dg < D_ / 4; ++dg) {
            float4 kv = k4[dg];
            float4 qv = q4[dg];
            dot2_step(qv.x, kv.x, s, c);
            dot2_step(qv.y, kv.y, s, c);
            dot2_step(qv.z, kv.z, s, c);
            dot2_step(qv.w, kv.w, s, c);
        }
        cand_val[i] = ((double)s + (double)c) * 0.125;
    }
    __syncthreads();

    // Exact top-32 by warp 0 (max value, tie -> lower index; matches jax top_k)
    if (wid == 0) {
        for (int it = 0; it < TOPK_; ++it) {
            double bv = -1e308; int bi = 0x7FFFFFFF; int bs = -1;
            for (int i = lane; i < n; i += 32) {
                double cv = cand_val[i]; int ci = cand_idx[i];
                if (cv > bv || (cv == bv && ci < bi)) { bv = cv; bi = ci; bs = i; }
            }
            #pragma unroll
            for (int o = 16; o >= 1; o >>= 1) {
                double ov = __shfl_xor_sync(0xffffffffu, bv, o);
                int    oi = __shfl_xor_sync(0xffffffffu, bi, o);
                int    os = __shfl_xor_sync(0xffffffffu, bs, o);
                if (ov > bv || (ov == bv && oi < bi)) { bv = ov; bi = oi; bs = os; }
            }
            if (lane == 0) {
                sel_idx[it] = bi;
                sel_val[it] = (float)bv;
                if (bs >= 0) cand_val[bs] = -1e308;
            }
            __syncwarp();
        }
    }
    __syncthreads();

    // Output: out[row][d] = sum_j val_j * V[idx_j][d]
    if (t < D_) {
        const float* vb = v + (size_t)b * L_ * D_;
        float acc = 0.0f;
        #pragma unroll
        for (int j = 0; j < TOPK_; ++j)
            acc = fmaf(sel_val[j], vb[(size_t)sel_idx[j] * D_ + t], acc);
        out[(size_t)bid * D_ + t] = acc;
    }
}

// ---------------------------------------------------------------------------
extern "C" void kernel_launch(void* const* d_in, const int* in_sizes, int n_in,
                              void* d_out, int out_size)
{
    const float* q = (const float*)d_in[0];
    const float* k = (const float*)d_in[1];
    const float* v = (const float*)d_in[2];
    float* out = (float*)d_out;

    dim3 gridA(KSPLIT, L_ / TQ, B_);
    score_kernel<<<gridA, 256>>>(q, k);

    select_kernel<<<B_ * L_, 256>>>(q, k, v, out);
}

// round 3
// speedup vs baseline: 1.8151x; 1.8151x over previous
#include <cuda_runtime.h>
#include <cstdint>

// Problem constants
#define B_   8
#define L_   2048
#define D_   64
#define TOPK_ 32

// Score kernel tiling
#define TQ 64
#define CK 64
#define KSPLIT 2
#define KEYS_PER_BLK (L_ / KSPLIT)

// Selection
#define MINC   36      // minimum candidate count (rank-margin safety)
#define CAP    256     // candidate buffer capacity

// 134 MB global scratch for scores [B][Lq][Lk]
__device__ float g_scores[(size_t)B_ * L_ * L_];

// ---------------------------------------------------------------------------
// Kernel A: S[b][q][k] = dot(Q[b][q], K[b][k]) * 0.125 (fp32)
// grid (KSPLIT, L/TQ, B), block 256
// ---------------------------------------------------------------------------
__global__ __launch_bounds__(256) void score_kernel(
    const float* __restrict__ q, const float* __restrict__ k)
{
    __shared__ __align__(16) float Qs[TQ][68];
    __shared__ __align__(16) float Ks[CK][68];

    const int b  = blockIdx.z;
    const int qt = blockIdx.y;
    const int ks = blockIdx.x;
    const int rowBase = qt * TQ;

    const float* qb = q + ((size_t)b * L_ + rowBase) * D_;
    const float* kb = k + (size_t)b * L_ * D_;
    float* sb = g_scores + ((size_t)b * L_ + rowBase) * L_;

    const int t  = threadIdx.x;
    const int tx = t & 15;
    const int ty = t >> 4;

    for (int i = t; i < TQ * 16; i += 256) {
        int row = i >> 4, dg = (i & 15) << 2;
        *(float4*)&Qs[row][dg] = *(const float4*)(qb + row * D_ + dg);
    }
    __syncthreads();

    for (int chunk = 0; chunk < KEYS_PER_BLK / CK; ++chunk) {
        const int keyBase = ks * KEYS_PER_BLK + chunk * CK;
        for (int i = t; i < CK * 16; i += 256) {
            int row = i >> 4, dg = (i & 15) << 2;
            *(float4*)&Ks[row][dg] = *(const float4*)(kb + (size_t)(keyBase + row) * D_ + dg);
        }
        __syncthreads();

        float acc[4][4] = {};
        #pragma unroll
        for (int dg = 0; dg < D_; dg += 4) {
            float4 qv[4], kv[4];
            #pragma unroll
            for (int r = 0; r < 4; ++r) qv[r] = *(const float4*)&Qs[ty + 16 * r][dg];
            #pragma unroll
            for (int c = 0; c < 4; ++c) kv[c] = *(const float4*)&Ks[tx + 16 * c][dg];
            #pragma unroll
            for (int r = 0; r < 4; ++r)
                #pragma unroll
                for (int c = 0; c < 4; ++c) {
                    acc[r][c] = fmaf(qv[r].x, kv[c].x, acc[r][c]);
                    acc[r][c] = fmaf(qv[r].y, kv[c].y, acc[r][c]);
                    acc[r][c] = fmaf(qv[r].z, kv[c].z, acc[r][c]);
                    acc[r][c] = fmaf(qv[r].w, kv[c].w, acc[r][c]);
                }
        }

        #pragma unroll
        for (int r = 0; r < 4; ++r)
            #pragma unroll
            for (int c = 0; c < 4; ++c)
                sb[(size_t)(ty + 16 * r) * L_ + keyBase + tx + 16 * c] = acc[r][c] * 0.125f;
        __syncthreads();
    }
}

// ---------------------------------------------------------------------------
// Kernel B: per query row, 128 threads.
//  1) analytic threshold seed from ||q|| (1 counting pass typical)
//  2) collect candidates, refine with compensated float-float dot (fp64 order)
//  3) parallel rank -> exact top-32
//  4) accumulate output
// ---------------------------------------------------------------------------
__device__ __forceinline__ unsigned f2sortable(float f) {
    unsigned bb = __float_as_uint(f);
    return (bb & 0x80000000u) ? ~bb : (bb | 0x80000000u);
}

__device__ __forceinline__ void dot2_step(float a, float b, float& s, float& c) {
    float p  = __fmul_rn(a, b);
    float e  = __fmaf_rn(a, b, -p);
    float t1 = __fadd_rn(s, p);
    float bv = __fsub_rn(t1, s);
    float e2 = __fadd_rn(__fsub_rn(s, __fsub_rn(t1, bv)), __fsub_rn(p, bv));
    s = t1;
    c = __fadd_rn(c, __fadd_rn(e, e2));
}

__global__ __launch_bounds__(128) void select_kernel(
    const float* __restrict__ q, const float* __restrict__ k,
    const float* __restrict__ v, float* __restrict__ out)
{
    const int bid  = blockIdx.x;
    const int b    = bid >> 11;
    const int t    = threadIdx.x;
    const int lane = t & 31;
    const int wid  = t >> 5;

    __shared__ __align__(16) float qs[D_];
    __shared__ unsigned tau0_sh;
    __shared__ int     warp_cnt[4];
    __shared__ int     cand_idx[CAP];
    __shared__ double  cand_val[CAP];
    __shared__ int     sh_cnt;
    __shared__ int     sel_idx[TOPK_];
    __shared__ float   sel_val[TOPK_];

    const float* srow = g_scores + (size_t)bid * L_;

    // Each thread owns 16 scores: 4 coalesced float4 groups
    unsigned u[16];
    #pragma unroll
    for (int g = 0; g < 4; ++g) {
        float4 s = *(const float4*)(srow + g * 512 + 4 * t);
        u[4 * g + 0] = f2sortable(s.x);
        u[4 * g + 1] = f2sortable(s.y);
        u[4 * g + 2] = f2sortable(s.z);
        u[4 * g + 3] = f2sortable(s.w);
    }

    if (t < D_) qs[t] = q[(size_t)bid * D_ + t];
    if (t == 0) sh_cnt = 0;
    __syncthreads();

    // analytic threshold: scores ~ N(0, ||q||^2/64); tau = 1.95*||q||/8
    if (wid == 0) {
        float x = qs[lane], y = qs[lane + 32];
        float s = x * x + y * y;
        #pragma unroll
        for (int o = 16; o >= 1; o >>= 1) s += __shfl_xor_sync(0xffffffffu, s, o);
        if (lane == 0) tau0_sh = f2sortable(1.95f * sqrtf(s) * 0.125f);
    }
    __syncthreads();

    unsigned lo = 0u, hi = 0xFFFFFFFFu, mid = tau0_sh, tau = 0u;
    for (int it = 0; it < 36; ++it) {
        int c = 0;
        #pragma unroll
        for (int j = 0; j < 16; ++j) c += (u[j] >= mid);
        #pragma unroll
        for (int o = 16; o >= 1; o >>= 1) c += __shfl_xor_sync(0xffffffffu, c, o);
        if (lane == 0) warp_cnt[wid] = c;
        __syncthreads();
        int total = warp_cnt[0] + warp_cnt[1] + warp_cnt[2] + warp_cnt[3];
        if (total >= MINC && total <= CAP) { tau = mid; break; }
        if (total < MINC) hi = mid; else { lo = mid; tau = mid; }
        mid = lo + ((hi - lo) >> 1);
        __syncthreads();
    }
    __syncthreads();

    // Collect candidates
    #pragma unroll
    for (int j = 0; j < 16; ++j) {
        if (u[j] >= tau) {
            int p = atomicAdd(&sh_cnt, 1);
            if (p < CAP) cand_idx[p] = (j >> 2) * 512 + 4 * t + (j & 3);
        }
    }
    __syncthreads();
    int n = sh_cnt; if (n > CAP) n = CAP;

    // Refine with compensated dot (matches fp64 ordering)
    const float* kb = k + (size_t)b * L_ * D_;
    for (int i = t; i < n; i += 128) {
        const float4* k4 = (const float4*)(kb + (size_t)cand_idx[i] * D_);
        const float4* q4 = (const float4*)qs;
        float s = 0.0f, c = 0.0f;
        #pragma unroll
        for (int dg = 0; dg < D_ / 4; ++dg) {
            float4 kv = k4[dg];
            float4 qv = q4[dg];
            dot2_step(qv.x, kv.x, s, c);
            dot2_step(qv.y, kv.y, s, c);
            dot2_step(qv.z, kv.z, s, c);
            dot2_step(qv.w, kv.w, s, c);
        }
        cand_val[i] = ((double)s + (double)c) * 0.125;
    }
    __syncthreads();

    // Parallel rank -> exact top-32 (val desc, tie -> lower index)
    for (int i = t; i < n; i += 128) {
        double vi = cand_val[i];
        int    ii = cand_idx[i];
        int rank = 0;
        for (int j = 0; j < n; ++j) {
            double vj = cand_val[j];
            int    ij = cand_idx[j];
            rank += (vj > vi) || (vj == vi && ij < ii);
        }
        if (rank < TOPK_) {
            sel_idx[rank] = ii;
            sel_val[rank] = (float)vi;
        }
    }
    __syncthreads();

    // Output: out[row][d] = sum_j val_j * V[idx_j][d]
    if (t < D_) {
        const float* vb = v + (size_t)b * L_ * D_;
        float acc = 0.0f;
        #pragma unroll
        for (int j = 0; j < TOPK_; ++j)
            acc = fmaf(sel_val[j], vb[(size_t)sel_idx[j] * D_ + t], acc);
        out[(size_t)bid * D_ + t] = acc;
    }
}

// ---------------------------------------------------------------------------
extern "C" void kernel_launch(void* const* d_in, const int* in_sizes, int n_in,
                              void* d_out, int out_size)
{
    const float* q = (const float*)d_in[0];
    const float* k = (const float*)d_in[1];
    const float* v = (const float*)d_in[2];
    float* out = (float*)d_out;

    dim3 gridA(KSPLIT, L_ / TQ, B_);
    score_kernel<<<gridA, 256>>>(q, k);

    select_kernel<<<B_ * L_, 128>>>(q, k, v, out);
}